// round 16
// baseline (speedup 1.0000x reference)
#include <cuda_runtime.h>
#include <math.h>
#include <stdint.h>

#define N_NODES 50000
#define N_EDGES 800000
#define HID     128
#define N_GRAPHS 32
#define LN_EPS  1e-5f
#define NB      148          // co-resident blocks for cooperative CSR build

// ---------------- scratch (device globals; no allocation allowed) ------------
__device__ float g_hcur [N_NODES * HID];
__device__ float g_hfeat[N_NODES * HID];
__device__ float g_skip [N_NODES * HID];
__device__ float g_esrc [N_NODES];
__device__ float g_edst [N_NODES];
__device__ float g_psum [N_GRAPHS * HID];
__device__ float g_pmax [N_GRAPHS * HID];
__device__ float g_cnt  [N_GRAPHS];
// CSR scratch
__device__ int   g_deg     [N_NODES];
__device__ int   g_rowstart[N_NODES + 1];
__device__ int   g_cursor  [N_NODES];
__device__ int   g_blksum  [NB];
__device__ int   g_blkoff  [NB];
__device__ int   g_csr_src [N_EDGES];
// grid barrier state
__device__ unsigned          g_barcnt = 0;
__device__ volatile unsigned g_bargen = 0;

// ---------------- helpers ------------------------------------------------------
__device__ __forceinline__ void atomicMaxF(float* a, float v) {
    if (v >= 0.f) atomicMax((int*)a, __float_as_int(v));
    else          atomicMin((unsigned int*)a, __float_as_uint(v));
}

__device__ __forceinline__ void redAddV4(float* dst, float a, float b, float c, float d) {
    asm volatile("red.global.add.v4.f32 [%0], {%1,%2,%3,%4};"
                 :: "l"(dst), "f"(a), "f"(b), "f"(c), "f"(d) : "memory");
}

__device__ __forceinline__ void gridbar() {
    __syncthreads();
    if (threadIdx.x == 0) {
        __threadfence();
        unsigned g = g_bargen;
        unsigned old = atomicInc(&g_barcnt, NB - 1);
        if (old == NB - 1) g_bargen = g + 1;
        else while (g_bargen == g) { __nanosleep(64); }
    }
    __syncthreads();
}

// packed fp32x2 (sm_103a)
__device__ __forceinline__ unsigned long long pk2(float a, float b) {
    unsigned long long r;
    asm("mov.b64 %0, {%1, %2};" : "=l"(r) : "f"(a), "f"(b));
    return r;
}
__device__ __forceinline__ void fma2(unsigned long long& d,
                                     unsigned long long a, unsigned long long b) {
    asm("fma.rn.f32x2 %0, %1, %2, %0;" : "+l"(d) : "l"(a), "l"(b));
}
__device__ __forceinline__ float2 upk2(unsigned long long v) {
    float2 f;
    asm("mov.b64 {%0, %1}, %2;" : "=f"(f.x), "=f"(f.y) : "l"(v));
    return f;
}

__device__ __forceinline__ uint32_t smem_u32(const void* p) {
    uint32_t a;
    asm("{ .reg .u64 t; cvta.to.shared.u64 t, %1; cvt.u32.u64 %0, t; }"
        : "=r"(a) : "l"(p));
    return a;
}

// =============================================================================
// Dual GEMM (layer 0 + skip share the X tile) — measured 81us.
// =============================================================================
__global__ void __launch_bounds__(256) gemm128_dual(
    const float* __restrict__ X,
    const float* __restrict__ W0,
    const float* __restrict__ Wsk, const float* __restrict__ bsk,
    const float* __restrict__ a_s, const float* __restrict__ a_d,
    float* __restrict__ H, float* __restrict__ SK,
    float* __restrict__ es, float* __restrict__ ed,
    int n)
{
    __shared__ float sW [32 * 128];
    __shared__ float sW2[32 * 128];
    __shared__ float sXT[32 * 64];

    const int tid  = threadIdx.x;
    const int warp = tid >> 5;
    const int lane = tid & 31;
    const int row0 = blockIdx.x * 64;

    unsigned long long a01[8], a23[8], b01[8], b23[8];
#pragma unroll
    for (int r = 0; r < 8; r++) { a01[r]=0ull; a23[r]=0ull; b01[r]=0ull; b23[r]=0ull; }

    for (int k0 = 0; k0 < 128; k0 += 32) {
#pragma unroll
        for (int i = 0; i < 4; i++) {
            int idx = tid + i * 256;
            ((float4*)sW )[idx] = ((const float4*)(W0  + k0 * 128))[idx];
            ((float4*)sW2)[idx] = ((const float4*)(Wsk + k0 * 128))[idx];
        }
#pragma unroll
        for (int i = 0; i < 2; i++) {
            int t   = tid + i * 256;
            int row = t & 63;
            int c4  = t >> 6;
            int grow = row0 + row;
            float4 v = make_float4(0.f, 0.f, 0.f, 0.f);
            if (grow < n) v = ((const float4*)(X + grow * 128 + k0))[c4];
            sXT[(c4 * 4 + 0) * 64 + row] = v.x;
            sXT[(c4 * 4 + 1) * 64 + row] = v.y;
            sXT[(c4 * 4 + 2) * 64 + row] = v.z;
            sXT[(c4 * 4 + 3) * 64 + row] = v.w;
        }
        __syncthreads();

#pragma unroll
        for (int k = 0; k < 32; k++) {
            float4 w4 = *(const float4*)(sW  + k * 128 + lane * 4);
            float4 u4 = *(const float4*)(sW2 + k * 128 + lane * 4);
            float4 xa = *(const float4*)(sXT + k * 64  + warp * 8);
            float4 xb = *(const float4*)(sXT + k * 64  + warp * 8 + 4);
            unsigned long long w01 = pk2(w4.x, w4.y);
            unsigned long long w23 = pk2(w4.z, w4.w);
            unsigned long long u01 = pk2(u4.x, u4.y);
            unsigned long long u23 = pk2(u4.z, u4.w);
            float xv[8] = {xa.x, xa.y, xa.z, xa.w, xb.x, xb.y, xb.z, xb.w};
#pragma unroll
            for (int r = 0; r < 8; r++) {
                unsigned long long xx = pk2(xv[r], xv[r]);
                fma2(a01[r], xx, w01);
                fma2(a23[r], xx, w23);
                fma2(b01[r], xx, u01);
                fma2(b23[r], xx, u23);
            }
        }
        __syncthreads();
    }

    float4 as4 = *(const float4*)(a_s + lane * 4);
    float4 ad4 = *(const float4*)(a_d + lane * 4);
    float4 bk4 = *(const float4*)(bsk + lane * 4);

#pragma unroll
    for (int r = 0; r < 8; r++) {
        int row = row0 + warp * 8 + r;
        if (row < n) {
            float2 p01 = upk2(a01[r]);
            float2 p23 = upk2(a23[r]);
            float4 h = make_float4(p01.x, p01.y, p23.x, p23.y);
            *(float4*)(H + (long)row * 128 + lane * 4) = h;

            float2 q01 = upk2(b01[r]);
            float2 q23 = upk2(b23[r]);
            float4 sk = make_float4(q01.x + bk4.x, q01.y + bk4.y,
                                    q23.x + bk4.z, q23.y + bk4.w);
            *(float4*)(SK + (long)row * 128 + lane * 4) = sk;

            float ps = h.x * as4.x + h.y * as4.y + h.z * as4.z + h.w * as4.w;
            float pd = h.x * ad4.x + h.y * ad4.y + h.z * ad4.z + h.w * ad4.w;
#pragma unroll
            for (int o = 16; o > 0; o >>= 1) {
                ps += __shfl_xor_sync(0xffffffff, ps, o);
                pd += __shfl_xor_sync(0xffffffff, pd, o);
            }
            if (lane == 0) { es[row] = ps; ed[row] = pd; }
        }
    }
}

// =============================================================================
// Pipelined GEMM (layers 1-3) — launch_bounds(256,3), measured 43.6us.
// =============================================================================
__device__ __forceinline__ void cp16(uint32_t saddr, const void* g) {
    asm volatile("cp.async.cg.shared.global [%0], [%1], 16;"
                 :: "r"(saddr), "l"(g) : "memory");
}
#define CP_COMMIT() asm volatile("cp.async.commit_group;" ::: "memory")
#define CP_WAIT0()  asm volatile("cp.async.wait_group 0;" ::: "memory")

__global__ void __launch_bounds__(256, 3) gemm128(
    const float* __restrict__ X, const float* __restrict__ W,
    const float* __restrict__ a_s, const float* __restrict__ a_d,
    float* __restrict__ H, float* __restrict__ es, float* __restrict__ ed,
    int n)
{
    __shared__ float sW [2][32 * 128];
    __shared__ float sXT[2][32 * 64];

    const int tid  = threadIdx.x;
    const int warp = tid >> 5;
    const int lane = tid & 31;
    const int row0 = blockIdx.x * 64;
    const uint32_t swb = smem_u32(&sW[0][0]);

    unsigned long long acc01[8], acc23[8];
#pragma unroll
    for (int r = 0; r < 8; r++) { acc01[r] = 0ull; acc23[r] = 0ull; }

    const int xr0 = tid & 63,          xc0 = tid >> 6;
    const int xr1 = (tid + 256) & 63,  xc1 = (tid + 256) >> 6;
    const int g0 = row0 + xr0, g1 = row0 + xr1;

#pragma unroll
    for (int i = 0; i < 4; i++) {
        int idx = tid + i * 256;
        cp16(swb + idx * 16, W + idx * 4);
    }
    CP_COMMIT();

    float4 xv0 = make_float4(0.f, 0.f, 0.f, 0.f);
    float4 xv1 = make_float4(0.f, 0.f, 0.f, 0.f);
    if (g0 < n) xv0 = ((const float4*)(X + (long)g0 * 128))[xc0];
    if (g1 < n) xv1 = ((const float4*)(X + (long)g1 * 128))[xc1];
    {
        float* d = &sXT[0][0];
        d[(xc0 * 4 + 0) * 64 + xr0] = xv0.x;
        d[(xc0 * 4 + 1) * 64 + xr0] = xv0.y;
        d[(xc0 * 4 + 2) * 64 + xr0] = xv0.z;
        d[(xc0 * 4 + 3) * 64 + xr0] = xv0.w;
        d[(xc1 * 4 + 0) * 64 + xr1] = xv1.x;
        d[(xc1 * 4 + 1) * 64 + xr1] = xv1.y;
        d[(xc1 * 4 + 2) * 64 + xr1] = xv1.z;
        d[(xc1 * 4 + 3) * 64 + xr1] = xv1.w;
    }
    CP_WAIT0();
    __syncthreads();

#pragma unroll
    for (int it = 0; it < 4; it++) {
        const int cur = it & 1;
        const int nxt = cur ^ 1;

        if (it < 3) {
            const float* Wn = W + (it + 1) * 32 * 128;
#pragma unroll
            for (int i = 0; i < 4; i++) {
                int idx = tid + i * 256;
                cp16(swb + nxt * 16384 + idx * 16, Wn + idx * 4);
            }
            CP_COMMIT();
            int k0 = (it + 1) * 32;
            xv0 = make_float4(0.f, 0.f, 0.f, 0.f);
            xv1 = make_float4(0.f, 0.f, 0.f, 0.f);
            if (g0 < n) xv0 = ((const float4*)(X + (long)g0 * 128 + k0))[xc0];
            if (g1 < n) xv1 = ((const float4*)(X + (long)g1 * 128 + k0))[xc1];
        }

        const float* wbase = &sW [cur][0];
        const float* xbase = &sXT[cur][0];
#pragma unroll
        for (int k = 0; k < 32; k++) {
            float4 w4 = *(const float4*)(wbase + k * 128 + lane * 4);
            float4 xa = *(const float4*)(xbase + k * 64  + warp * 8);
            float4 xb = *(const float4*)(xbase + k * 64  + warp * 8 + 4);
            unsigned long long w01 = pk2(w4.x, w4.y);
            unsigned long long w23 = pk2(w4.z, w4.w);
            float xv[8] = {xa.x, xa.y, xa.z, xa.w, xb.x, xb.y, xb.z, xb.w};
#pragma unroll
            for (int r = 0; r < 8; r++) {
                unsigned long long xx = pk2(xv[r], xv[r]);
                fma2(acc01[r], xx, w01);
                fma2(acc23[r], xx, w23);
            }
        }

        if (it < 3) {
            float* d = &sXT[nxt][0];
            d[(xc0 * 4 + 0) * 64 + xr0] = xv0.x;
            d[(xc0 * 4 + 1) * 64 + xr0] = xv0.y;
            d[(xc0 * 4 + 2) * 64 + xr0] = xv0.z;
            d[(xc0 * 4 + 3) * 64 + xr0] = xv0.w;
            d[(xc1 * 4 + 0) * 64 + xr1] = xv1.x;
            d[(xc1 * 4 + 1) * 64 + xr1] = xv1.y;
            d[(xc1 * 4 + 2) * 64 + xr1] = xv1.z;
            d[(xc1 * 4 + 3) * 64 + xr1] = xv1.w;
            CP_WAIT0();
            __syncthreads();
        }
    }

    float4 as4 = *(const float4*)(a_s + lane * 4);
    float4 ad4 = *(const float4*)(a_d + lane * 4);

#pragma unroll
    for (int r = 0; r < 8; r++) {
        int row = row0 + warp * 8 + r;
        if (row < n) {
            float2 p01 = upk2(acc01[r]);
            float2 p23 = upk2(acc23[r]);
            float4 h = make_float4(p01.x, p01.y, p23.x, p23.y);
            *(float4*)(H + (long)row * 128 + lane * 4) = h;
            float ps = h.x * as4.x + h.y * as4.y + h.z * as4.z + h.w * as4.w;
            float pd = h.x * ad4.x + h.y * ad4.y + h.z * ad4.z + h.w * ad4.w;
#pragma unroll
            for (int o = 16; o > 0; o >>= 1) {
                ps += __shfl_xor_sync(0xffffffff, ps, o);
                pd += __shfl_xor_sync(0xffffffff, pd, o);
            }
            if (lane == 0) { es[row] = ps; ed[row] = pd; }
        }
    }
}

// =============================================================================
// Cooperative CSR build (dst-major), int4-vectorized, pool-init fused.
// Measured 32us.
// =============================================================================
__global__ void __launch_bounds__(256) csr_build(const int* __restrict__ ei) {
    const int tid = threadIdx.x;
    const int b   = blockIdx.x;
    const int gt  = b * 256 + tid;
    const int nt  = NB * 256;

    for (int i = gt; i < N_NODES; i += nt) g_deg[i] = 0;
    if (gt < N_GRAPHS * HID) {
        g_psum[gt] = 0.f;
        g_pmax[gt] = __int_as_float(0xFF800000);   // -inf
    }
    if (gt < N_GRAPHS) g_cnt[gt] = 0.f;
    gridbar();

    for (int e4 = gt * 4; e4 < N_EDGES; e4 += nt * 4) {
        int4 d4 = *(const int4*)(ei + N_EDGES + e4);
        atomicAdd(&g_deg[d4.x], 1);
        atomicAdd(&g_deg[d4.y], 1);
        atomicAdd(&g_deg[d4.z], 1);
        atomicAdd(&g_deg[d4.w], 1);
    }
    gridbar();

    {
        int n0 = b * 512 + tid * 2;
        int v0 = (n0     < N_NODES) ? g_deg[n0]     : 0;
        int v1 = (n0 + 1 < N_NODES) ? g_deg[n0 + 1] : 0;
        int tsum = v0 + v1;
        int lane = tid & 31, wid = tid >> 5;
        int x = tsum;
#pragma unroll
        for (int o = 1; o < 32; o <<= 1) {
            int y = __shfl_up_sync(0xffffffff, x, o);
            if (lane >= o) x += y;
        }
        __shared__ int wsum[8];
        if (lane == 31) wsum[wid] = x;
        __syncthreads();
        if (tid < 8) {
            int y = wsum[tid];
#pragma unroll
            for (int o = 1; o < 8; o <<= 1) {
                int z2 = __shfl_up_sync(0xff, y, o);
                if (tid >= o) y += z2;
            }
            wsum[tid] = y;
        }
        __syncthreads();
        int excl = x - tsum + (wid > 0 ? wsum[wid - 1] : 0);
        if (tid == 255) g_blksum[b] = wsum[7];
        if (n0     < N_NODES) g_rowstart[n0]     = excl;
        if (n0 + 1 < N_NODES) g_rowstart[n0 + 1] = excl + v0;
    }
    gridbar();

    if (b == 0) {
        __shared__ int sc[256];
        int v = (tid < NB) ? g_blksum[tid] : 0;
        sc[tid] = v;
        __syncthreads();
#pragma unroll
        for (int o = 1; o < 256; o <<= 1) {
            int y = (tid >= o) ? sc[tid - o] : 0;
            __syncthreads();
            sc[tid] += y;
            __syncthreads();
        }
        if (tid < NB) g_blkoff[tid] = sc[tid] - v;
    }
    gridbar();

    for (int i = gt; i < N_NODES; i += nt) {
        int r = g_rowstart[i] + g_blkoff[i >> 9];
        g_rowstart[i] = r;
        g_cursor[i]   = r;
    }
    if (gt == 0) g_rowstart[N_NODES] = N_EDGES;
    gridbar();

    for (int e4 = gt * 4; e4 < N_EDGES; e4 += nt * 4) {
        int4 s4 = *(const int4*)(ei + e4);
        int4 d4 = *(const int4*)(ei + N_EDGES + e4);
        int p0 = atomicAdd(&g_cursor[d4.x], 1);
        int p1 = atomicAdd(&g_cursor[d4.y], 1);
        int p2 = atomicAdd(&g_cursor[d4.z], 1);
        int p3 = atomicAdd(&g_cursor[d4.w], 1);
        g_csr_src[p0] = s4.x;
        g_csr_src[p1] = s4.y;
        g_csr_src[p2] = s4.z;
        g_csr_src[p3] = s4.w;
    }
}

// =============================================================================
// Fused layer with f32x2-packed accumulation (measured 41.0us): softmax +
// gather + bias + LN + ELU + skip (+ pooling on layer 3). Warp per node.
// =============================================================================
__device__ __forceinline__ float edge_p(float esrc, float edst) {
    float v = esrc + edst;
    v = fmaxf(v, 0.2f * v);
    return __expf(v);
}

__global__ void __launch_bounds__(256) gat_layer(
    const float* __restrict__ gat_b, const float* __restrict__ ln_g,
    const float* __restrict__ ln_b, const int* __restrict__ batch, int layer)
{
    int w = (blockIdx.x * blockDim.x + threadIdx.x) >> 5;
    int lane = threadIdx.x & 31;
    if (w >= N_NODES) return;

    float ed = __ldg(g_edst + w);

    float p = edge_p(__ldg(g_esrc + w), ed);
    float z = p;
    unsigned long long aXY = 0ull, aZW = 0ull;
    {
        ulonglong2 hs = *(const ulonglong2*)(g_hfeat + (long)w * 128 + lane * 4);
        unsigned long long pp = pk2(p, p);
        fma2(aXY, pp, hs.x);
        fma2(aZW, pp, hs.y);
    }

    int i   = __ldg(g_rowstart + w);
    int end = __ldg(g_rowstart + w + 1);

    for (; i + 4 <= end; i += 4) {
        int s0 = __ldg(g_csr_src + i);
        int s1 = __ldg(g_csr_src + i + 1);
        int s2 = __ldg(g_csr_src + i + 2);
        int s3 = __ldg(g_csr_src + i + 3);
        float p0 = edge_p(__ldg(g_esrc + s0), ed);
        float p1 = edge_p(__ldg(g_esrc + s1), ed);
        float p2 = edge_p(__ldg(g_esrc + s2), ed);
        float p3 = edge_p(__ldg(g_esrc + s3), ed);
        ulonglong2 h0 = *(const ulonglong2*)(g_hfeat + (long)s0 * 128 + lane * 4);
        ulonglong2 h1 = *(const ulonglong2*)(g_hfeat + (long)s1 * 128 + lane * 4);
        ulonglong2 h2 = *(const ulonglong2*)(g_hfeat + (long)s2 * 128 + lane * 4);
        ulonglong2 h3 = *(const ulonglong2*)(g_hfeat + (long)s3 * 128 + lane * 4);
        z += (p0 + p1) + (p2 + p3);
        unsigned long long q0 = pk2(p0, p0);
        unsigned long long q1 = pk2(p1, p1);
        unsigned long long q2 = pk2(p2, p2);
        unsigned long long q3 = pk2(p3, p3);
        fma2(aXY, q0, h0.x); fma2(aZW, q0, h0.y);
        fma2(aXY, q1, h1.x); fma2(aZW, q1, h1.y);
        fma2(aXY, q2, h2.x); fma2(aZW, q2, h2.y);
        fma2(aXY, q3, h3.x); fma2(aZW, q3, h3.y);
    }
    for (; i < end; i++) {
        int s0 = __ldg(g_csr_src + i);
        float p0 = edge_p(__ldg(g_esrc + s0), ed);
        ulonglong2 h0 = *(const ulonglong2*)(g_hfeat + (long)s0 * 128 + lane * 4);
        z += p0;
        unsigned long long q0 = pk2(p0, p0);
        fma2(aXY, q0, h0.x); fma2(aZW, q0, h0.y);
    }

    float2 axy = upk2(aXY);
    float2 azw = upk2(aZW);
    float inv = __fdividef(1.f, z);
    float4 b4 = *(const float4*)(gat_b + lane * 4);
    float4 v;
    v.x = axy.x * inv + b4.x;
    v.y = axy.y * inv + b4.y;
    v.z = azw.x * inv + b4.z;
    v.w = azw.y * inv + b4.w;

    float s  = v.x + v.y + v.z + v.w;
    float sq = v.x * v.x + v.y * v.y + v.z * v.z + v.w * v.w;
#pragma unroll
    for (int o = 16; o > 0; o >>= 1) {
        s  += __shfl_xor_sync(0xffffffff, s,  o);
        sq += __shfl_xor_sync(0xffffffff, sq, o);
    }
    float mean = s * (1.f / 128.f);
    float var  = sq * (1.f / 128.f) - mean * mean;
    float rstd = rsqrtf(var + LN_EPS);

    float4 g4 = *(const float4*)(ln_g + lane * 4);
    float4 l4 = *(const float4*)(ln_b + lane * 4);
    float y0 = (v.x - mean) * rstd * g4.x + l4.x;
    float y1 = (v.y - mean) * rstd * g4.y + l4.y;
    float y2 = (v.z - mean) * rstd * g4.z + l4.z;
    float y3 = (v.w - mean) * rstd * g4.w + l4.w;

    if (layer < 3) {
        y0 = y0 > 0.f ? y0 : expm1f(y0);
        y1 = y1 > 0.f ? y1 : expm1f(y1);
        y2 = y2 > 0.f ? y2 : expm1f(y2);
        y3 = y3 > 0.f ? y3 : expm1f(y3);
    }

    const float* skp = (layer == 0) ? g_skip : g_hcur;
    float4 sk = *(const float4*)(skp + (long)w * 128 + lane * 4);
    y0 += sk.x; y1 += sk.y; y2 += sk.z; y3 += sk.w;

    *(float4*)(g_hcur + (long)w * 128 + lane * 4) = make_float4(y0, y1, y2, y3);

    if (layer == 3) {
        int g = __ldg(batch + w);
        redAddV4(g_psum + g * 128 + lane * 4, y0, y1, y2, y3);
        float* pm = g_pmax + g * 128 + lane * 4;
        atomicMaxF(pm + 0, y0);
        atomicMaxF(pm + 1, y1);
        atomicMaxF(pm + 2, y2);
        atomicMaxF(pm + 3, y3);
        if (lane == 0) atomicAdd(&g_cnt[g], 1.f);
    }
}

// ---------------- MLP head (one block per graph) ------------------------------
__global__ void __launch_bounds__(128) mlp_head(
    const float* __restrict__ W1, const float* __restrict__ b1,
    const float* __restrict__ W2, const float* __restrict__ b2,
    const float* __restrict__ W3, const float* __restrict__ b3,
    float* __restrict__ out)
{
    __shared__ float gv[256];
    __shared__ float h1[128];
    __shared__ float h2[64];
    int g = blockIdx.x, t = threadIdx.x;

    float cnt = fmaxf(g_cnt[g], 1.f);
    gv[t]       = g_psum[g * 128 + t] / cnt;
    gv[128 + t] = g_pmax[g * 128 + t];
    __syncthreads();

    float a1 = b1[t];
#pragma unroll 8
    for (int k = 0; k < 256; k++) a1 += gv[k] * W1[k * 128 + t];
    h1[t] = fmaxf(a1, 0.f);
    __syncthreads();

    if (t < 64) {
        float a2 = b2[t];
#pragma unroll 8
        for (int k = 0; k < 128; k++) a2 += h1[k] * W2[k * 64 + t];
        h2[t] = fmaxf(a2, 0.f);
    }
    __syncthreads();

    if (t < 4) {
        float a3 = b3[t];
#pragma unroll
        for (int k = 0; k < 64; k++) a3 += h2[k] * W3[k * 4 + t];
        out[g * 4 + t] = a3;
    }
}

// ---------------- launch ------------------------------------------------------
extern "C" void kernel_launch(void* const* d_in, const int* in_sizes, int n_in,
                              void* d_out, int out_size)
{
    const float* x      = (const float*)d_in[0];
    const int*   ei     = (const int*)  d_in[1];
    const int*   batch  = (const int*)  d_in[2];
    const float* Ws     = (const float*)d_in[3];
    const float* a_src  = (const float*)d_in[4];
    const float* a_dst  = (const float*)d_in[5];
    const float* gat_b  = (const float*)d_in[6];
    const float* ln_g   = (const float*)d_in[7];
    const float* ln_b   = (const float*)d_in[8];
    const float* skip_W = (const float*)d_in[9];
    const float* skip_b = (const float*)d_in[10];
    const float* W1 = (const float*)d_in[11];
    const float* b1 = (const float*)d_in[12];
    const float* W2 = (const float*)d_in[13];
    const float* b2 = (const float*)d_in[14];
    const float* W3 = (const float*)d_in[15];
    const float* b3 = (const float*)d_in[16];

    float *hcur, *hfeat, *skip, *esrc, *edst;
    cudaGetSymbolAddress((void**)&hcur,  g_hcur);
    cudaGetSymbolAddress((void**)&hfeat, g_hfeat);
    cudaGetSymbolAddress((void**)&skip,  g_skip);
    cudaGetSymbolAddress((void**)&esrc,  g_esrc);
    cudaGetSymbolAddress((void**)&edst,  g_edst);

    const int gemm_blocks = (N_NODES + 63) / 64;
    const int node_blocks = (N_NODES * 32 + 255) / 256;   // warp per node

    // lazily-created aux stream + fork/join events (host objects only;
    // per-call device work is identical on every call)
    static cudaStream_t s_aux = nullptr;
    static cudaEvent_t  s_fork = nullptr, s_join = nullptr;
    if (!s_aux) {
        cudaStreamCreateWithFlags(&s_aux, cudaStreamNonBlocking);
        cudaEventCreateWithFlags(&s_fork, cudaEventDisableTiming);
        cudaEventCreateWithFlags(&s_join, cudaEventDisableTiming);
    }

    // fork: csr_build (aux) || dual GEMM (main) — no data dependency
    cudaEventRecord(s_fork, 0);
    cudaStreamWaitEvent(s_aux, s_fork, 0);
    csr_build<<<NB, 256, 0, s_aux>>>(ei);
    cudaEventRecord(s_join, s_aux);

    gemm128_dual<<<gemm_blocks, 256>>>(x, Ws, skip_W, skip_b,
                                       a_src, a_dst,
                                       hfeat, skip, esrc, edst, N_NODES);

    // join: gat_layer(0) needs BOTH csr and dual results
    cudaStreamWaitEvent(0, s_join, 0);
    gat_layer<<<node_blocks, 256>>>(gat_b, ln_g, ln_b, batch, 0);

    for (int l = 1; l < 4; l++) {
        gemm128<<<gemm_blocks, 256>>>(hcur, Ws + l * 128 * 128,
                                      a_src + l * 128, a_dst + l * 128,
                                      hfeat, esrc, edst, N_NODES);
        gat_layer<<<node_blocks, 256>>>(gat_b + l * 128, ln_g + l * 128,
                                        ln_b + l * 128, batch, l);
    }

    mlp_head<<<N_GRAPHS, 128>>>(W1, b1, W2, b2, W3, b3, (float*)d_out);
}

// round 17
// speedup vs baseline: 1.0239x; 1.0239x over previous
#include <cuda_runtime.h>
#include <math.h>
#include <stdint.h>

#define N_NODES 50000
#define N_EDGES 800000
#define HID     128
#define N_GRAPHS 32
#define LN_EPS  1e-5f
#define SCAN_BLK ((N_NODES + 1023) / 1024)   // 49

// ---------------- scratch (device globals; no allocation allowed) ------------
__device__ float g_hcur [N_NODES * HID];
__device__ float g_hfeat[N_NODES * HID];
__device__ float g_skip [N_NODES * HID];
__device__ float g_esrc [N_NODES];
__device__ float g_edst [N_NODES];
__device__ float g_psum [N_GRAPHS * HID];
__device__ float g_pmax [N_GRAPHS * HID];
__device__ float g_cnt  [N_GRAPHS];
// CSR scratch
__device__ int   g_deg     [N_NODES];
__device__ int   g_rowstart[N_NODES + 1];
__device__ int   g_cursor  [N_NODES];
__device__ int   g_blksum  [SCAN_BLK];
__device__ int   g_blkoff  [SCAN_BLK];
__device__ int   g_csr_src [N_EDGES];

// ---------------- helpers ------------------------------------------------------
__device__ __forceinline__ void atomicMaxF(float* a, float v) {
    if (v >= 0.f) atomicMax((int*)a, __float_as_int(v));
    else          atomicMin((unsigned int*)a, __float_as_uint(v));
}

__device__ __forceinline__ void redAddV4(float* dst, float a, float b, float c, float d) {
    asm volatile("red.global.add.v4.f32 [%0], {%1,%2,%3,%4};"
                 :: "l"(dst), "f"(a), "f"(b), "f"(c), "f"(d) : "memory");
}

// packed fp32x2 (sm_103a)
__device__ __forceinline__ unsigned long long pk2(float a, float b) {
    unsigned long long r;
    asm("mov.b64 %0, {%1, %2};" : "=l"(r) : "f"(a), "f"(b));
    return r;
}
__device__ __forceinline__ void fma2(unsigned long long& d,
                                     unsigned long long a, unsigned long long b) {
    asm("fma.rn.f32x2 %0, %1, %2, %0;" : "+l"(d) : "l"(a), "l"(b));
}
__device__ __forceinline__ float2 upk2(unsigned long long v) {
    float2 f;
    asm("mov.b64 {%0, %1}, %2;" : "=f"(f.x), "=f"(f.y) : "l"(v));
    return f;
}

__device__ __forceinline__ uint32_t smem_u32(const void* p) {
    uint32_t a;
    asm("{ .reg .u64 t; cvta.to.shared.u64 t, %1; cvt.u32.u64 %0, t; }"
        : "=r"(a) : "l"(p));
    return a;
}

// =============================================================================
// Dual GEMM (layer 0 + skip share the X tile) — measured 81us.
// =============================================================================
__global__ void __launch_bounds__(256) gemm128_dual(
    const float* __restrict__ X,
    const float* __restrict__ W0,
    const float* __restrict__ Wsk, const float* __restrict__ bsk,
    const float* __restrict__ a_s, const float* __restrict__ a_d,
    float* __restrict__ H, float* __restrict__ SK,
    float* __restrict__ es, float* __restrict__ ed,
    int n)
{
    __shared__ float sW [32 * 128];
    __shared__ float sW2[32 * 128];
    __shared__ float sXT[32 * 64];

    const int tid  = threadIdx.x;
    const int warp = tid >> 5;
    const int lane = tid & 31;
    const int row0 = blockIdx.x * 64;

    unsigned long long a01[8], a23[8], b01[8], b23[8];
#pragma unroll
    for (int r = 0; r < 8; r++) { a01[r]=0ull; a23[r]=0ull; b01[r]=0ull; b23[r]=0ull; }

    for (int k0 = 0; k0 < 128; k0 += 32) {
#pragma unroll
        for (int i = 0; i < 4; i++) {
            int idx = tid + i * 256;
            ((float4*)sW )[idx] = ((const float4*)(W0  + k0 * 128))[idx];
            ((float4*)sW2)[idx] = ((const float4*)(Wsk + k0 * 128))[idx];
        }
#pragma unroll
        for (int i = 0; i < 2; i++) {
            int t   = tid + i * 256;
            int row = t & 63;
            int c4  = t >> 6;
            int grow = row0 + row;
            float4 v = make_float4(0.f, 0.f, 0.f, 0.f);
            if (grow < n) v = ((const float4*)(X + grow * 128 + k0))[c4];
            sXT[(c4 * 4 + 0) * 64 + row] = v.x;
            sXT[(c4 * 4 + 1) * 64 + row] = v.y;
            sXT[(c4 * 4 + 2) * 64 + row] = v.z;
            sXT[(c4 * 4 + 3) * 64 + row] = v.w;
        }
        __syncthreads();

#pragma unroll
        for (int k = 0; k < 32; k++) {
            float4 w4 = *(const float4*)(sW  + k * 128 + lane * 4);
            float4 u4 = *(const float4*)(sW2 + k * 128 + lane * 4);
            float4 xa = *(const float4*)(sXT + k * 64  + warp * 8);
            float4 xb = *(const float4*)(sXT + k * 64  + warp * 8 + 4);
            unsigned long long w01 = pk2(w4.x, w4.y);
            unsigned long long w23 = pk2(w4.z, w4.w);
            unsigned long long u01 = pk2(u4.x, u4.y);
            unsigned long long u23 = pk2(u4.z, u4.w);
            float xv[8] = {xa.x, xa.y, xa.z, xa.w, xb.x, xb.y, xb.z, xb.w};
#pragma unroll
            for (int r = 0; r < 8; r++) {
                unsigned long long xx = pk2(xv[r], xv[r]);
                fma2(a01[r], xx, w01);
                fma2(a23[r], xx, w23);
                fma2(b01[r], xx, u01);
                fma2(b23[r], xx, u23);
            }
        }
        __syncthreads();
    }

    float4 as4 = *(const float4*)(a_s + lane * 4);
    float4 ad4 = *(const float4*)(a_d + lane * 4);
    float4 bk4 = *(const float4*)(bsk + lane * 4);

#pragma unroll
    for (int r = 0; r < 8; r++) {
        int row = row0 + warp * 8 + r;
        if (row < n) {
            float2 p01 = upk2(a01[r]);
            float2 p23 = upk2(a23[r]);
            float4 h = make_float4(p01.x, p01.y, p23.x, p23.y);
            *(float4*)(H + (long)row * 128 + lane * 4) = h;

            float2 q01 = upk2(b01[r]);
            float2 q23 = upk2(b23[r]);
            float4 sk = make_float4(q01.x + bk4.x, q01.y + bk4.y,
                                    q23.x + bk4.z, q23.y + bk4.w);
            *(float4*)(SK + (long)row * 128 + lane * 4) = sk;

            float ps = h.x * as4.x + h.y * as4.y + h.z * as4.z + h.w * as4.w;
            float pd = h.x * ad4.x + h.y * ad4.y + h.z * ad4.z + h.w * ad4.w;
#pragma unroll
            for (int o = 16; o > 0; o >>= 1) {
                ps += __shfl_xor_sync(0xffffffff, ps, o);
                pd += __shfl_xor_sync(0xffffffff, pd, o);
            }
            if (lane == 0) { es[row] = ps; ed[row] = pd; }
        }
    }
}

// =============================================================================
// Pipelined GEMM (layers 1-3) — launch_bounds(256,3), measured 43.6us.
// =============================================================================
__device__ __forceinline__ void cp16(uint32_t saddr, const void* g) {
    asm volatile("cp.async.cg.shared.global [%0], [%1], 16;"
                 :: "r"(saddr), "l"(g) : "memory");
}
#define CP_COMMIT() asm volatile("cp.async.commit_group;" ::: "memory")
#define CP_WAIT0()  asm volatile("cp.async.wait_group 0;" ::: "memory")

__global__ void __launch_bounds__(256, 3) gemm128(
    const float* __restrict__ X, const float* __restrict__ W,
    const float* __restrict__ a_s, const float* __restrict__ a_d,
    float* __restrict__ H, float* __restrict__ es, float* __restrict__ ed,
    int n)
{
    __shared__ float sW [2][32 * 128];
    __shared__ float sXT[2][32 * 64];

    const int tid  = threadIdx.x;
    const int warp = tid >> 5;
    const int lane = tid & 31;
    const int row0 = blockIdx.x * 64;
    const uint32_t swb = smem_u32(&sW[0][0]);

    unsigned long long acc01[8], acc23[8];
#pragma unroll
    for (int r = 0; r < 8; r++) { acc01[r] = 0ull; acc23[r] = 0ull; }

    const int xr0 = tid & 63,          xc0 = tid >> 6;
    const int xr1 = (tid + 256) & 63,  xc1 = (tid + 256) >> 6;
    const int g0 = row0 + xr0, g1 = row0 + xr1;

#pragma unroll
    for (int i = 0; i < 4; i++) {
        int idx = tid + i * 256;
        cp16(swb + idx * 16, W + idx * 4);
    }
    CP_COMMIT();

    float4 xv0 = make_float4(0.f, 0.f, 0.f, 0.f);
    float4 xv1 = make_float4(0.f, 0.f, 0.f, 0.f);
    if (g0 < n) xv0 = ((const float4*)(X + (long)g0 * 128))[xc0];
    if (g1 < n) xv1 = ((const float4*)(X + (long)g1 * 128))[xc1];
    {
        float* d = &sXT[0][0];
        d[(xc0 * 4 + 0) * 64 + xr0] = xv0.x;
        d[(xc0 * 4 + 1) * 64 + xr0] = xv0.y;
        d[(xc0 * 4 + 2) * 64 + xr0] = xv0.z;
        d[(xc0 * 4 + 3) * 64 + xr0] = xv0.w;
        d[(xc1 * 4 + 0) * 64 + xr1] = xv1.x;
        d[(xc1 * 4 + 1) * 64 + xr1] = xv1.y;
        d[(xc1 * 4 + 2) * 64 + xr1] = xv1.z;
        d[(xc1 * 4 + 3) * 64 + xr1] = xv1.w;
    }
    CP_WAIT0();
    __syncthreads();

#pragma unroll
    for (int it = 0; it < 4; it++) {
        const int cur = it & 1;
        const int nxt = cur ^ 1;

        if (it < 3) {
            const float* Wn = W + (it + 1) * 32 * 128;
#pragma unroll
            for (int i = 0; i < 4; i++) {
                int idx = tid + i * 256;
                cp16(swb + nxt * 16384 + idx * 16, Wn + idx * 4);
            }
            CP_COMMIT();
            int k0 = (it + 1) * 32;
            xv0 = make_float4(0.f, 0.f, 0.f, 0.f);
            xv1 = make_float4(0.f, 0.f, 0.f, 0.f);
            if (g0 < n) xv0 = ((const float4*)(X + (long)g0 * 128 + k0))[xc0];
            if (g1 < n) xv1 = ((const float4*)(X + (long)g1 * 128 + k0))[xc1];
        }

        const float* wbase = &sW [cur][0];
        const float* xbase = &sXT[cur][0];
#pragma unroll
        for (int k = 0; k < 32; k++) {
            float4 w4 = *(const float4*)(wbase + k * 128 + lane * 4);
            float4 xa = *(const float4*)(xbase + k * 64  + warp * 8);
            float4 xb = *(const float4*)(xbase + k * 64  + warp * 8 + 4);
            unsigned long long w01 = pk2(w4.x, w4.y);
            unsigned long long w23 = pk2(w4.z, w4.w);
            float xv[8] = {xa.x, xa.y, xa.z, xa.w, xb.x, xb.y, xb.z, xb.w};
#pragma unroll
            for (int r = 0; r < 8; r++) {
                unsigned long long xx = pk2(xv[r], xv[r]);
                fma2(acc01[r], xx, w01);
                fma2(acc23[r], xx, w23);
            }
        }

        if (it < 3) {
            float* d = &sXT[nxt][0];
            d[(xc0 * 4 + 0) * 64 + xr0] = xv0.x;
            d[(xc0 * 4 + 1) * 64 + xr0] = xv0.y;
            d[(xc0 * 4 + 2) * 64 + xr0] = xv0.z;
            d[(xc0 * 4 + 3) * 64 + xr0] = xv0.w;
            d[(xc1 * 4 + 0) * 64 + xr1] = xv1.x;
            d[(xc1 * 4 + 1) * 64 + xr1] = xv1.y;
            d[(xc1 * 4 + 2) * 64 + xr1] = xv1.z;
            d[(xc1 * 4 + 3) * 64 + xr1] = xv1.w;
            CP_WAIT0();
            __syncthreads();
        }
    }

    float4 as4 = *(const float4*)(a_s + lane * 4);
    float4 ad4 = *(const float4*)(a_d + lane * 4);

#pragma unroll
    for (int r = 0; r < 8; r++) {
        int row = row0 + warp * 8 + r;
        if (row < n) {
            float2 p01 = upk2(acc01[r]);
            float2 p23 = upk2(acc23[r]);
            float4 h = make_float4(p01.x, p01.y, p23.x, p23.y);
            *(float4*)(H + (long)row * 128 + lane * 4) = h;
            float ps = h.x * as4.x + h.y * as4.y + h.z * as4.z + h.w * as4.w;
            float pd = h.x * ad4.x + h.y * ad4.y + h.z * ad4.z + h.w * ad4.w;
#pragma unroll
            for (int o = 16; o > 0; o >>= 1) {
                ps += __shfl_xor_sync(0xffffffff, ps, o);
                pd += __shfl_xor_sync(0xffffffff, pd, o);
            }
            if (lane == 0) { es[row] = ps; ed[row] = pd; }
        }
    }
}

// =============================================================================
// CSR construction (multi-kernel, NO grid barrier — safe to overlap).
// int4-vectorized hist + scatter. pool_init fused into csr_zero.
// =============================================================================
__global__ void csr_zero() {
    int i = blockIdx.x * blockDim.x + threadIdx.x;
    if (i < N_NODES) g_deg[i] = 0;
    if (i < N_GRAPHS * HID) {
        g_psum[i] = 0.f;
        g_pmax[i] = __int_as_float(0xFF800000);  // -inf
    }
    if (i < N_GRAPHS) g_cnt[i] = 0.f;
}

__global__ void csr_hist(const int* __restrict__ ei) {
    int e4 = (blockIdx.x * blockDim.x + threadIdx.x) * 4;
    if (e4 >= N_EDGES) return;
    int4 d4 = *(const int4*)(ei + N_EDGES + e4);
    atomicAdd(&g_deg[d4.x], 1);
    atomicAdd(&g_deg[d4.y], 1);
    atomicAdd(&g_deg[d4.z], 1);
    atomicAdd(&g_deg[d4.w], 1);
}

__global__ void __launch_bounds__(1024) csr_scan1() {
    __shared__ int sh[1024];
    int i = blockIdx.x * 1024 + threadIdx.x;
    int v = (i < N_NODES) ? g_deg[i] : 0;
    sh[threadIdx.x] = v;
    __syncthreads();
#pragma unroll
    for (int off = 1; off < 1024; off <<= 1) {
        int t = (threadIdx.x >= off) ? sh[threadIdx.x - off] : 0;
        __syncthreads();
        sh[threadIdx.x] += t;
        __syncthreads();
    }
    if (i < N_NODES) g_rowstart[i] = sh[threadIdx.x] - v;   // exclusive
    if (threadIdx.x == 1023) g_blksum[blockIdx.x] = sh[1023];
}

__global__ void __launch_bounds__(64) csr_scan2() {
    __shared__ int sh[64];
    int t = threadIdx.x;
    int v = (t < SCAN_BLK) ? g_blksum[t] : 0;
    sh[t] = v;
    __syncthreads();
#pragma unroll
    for (int off = 1; off < 64; off <<= 1) {
        int u = (t >= off) ? sh[t - off] : 0;
        __syncthreads();
        sh[t] += u;
        __syncthreads();
    }
    if (t < SCAN_BLK) g_blkoff[t] = sh[t] - v;              // exclusive
}

__global__ void csr_scan3() {
    int i = blockIdx.x * blockDim.x + threadIdx.x;
    if (i < N_NODES) {
        int r = g_rowstart[i] + g_blkoff[i >> 10];
        g_rowstart[i] = r;
        g_cursor[i]   = r;
    }
    if (i == 0) g_rowstart[N_NODES] = N_EDGES;
}

__global__ void csr_scatter(const int* __restrict__ ei) {
    int e4 = (blockIdx.x * blockDim.x + threadIdx.x) * 4;
    if (e4 >= N_EDGES) return;
    int4 s4 = *(const int4*)(ei + e4);
    int4 d4 = *(const int4*)(ei + N_EDGES + e4);
    int p0 = atomicAdd(&g_cursor[d4.x], 1);
    int p1 = atomicAdd(&g_cursor[d4.y], 1);
    int p2 = atomicAdd(&g_cursor[d4.z], 1);
    int p3 = atomicAdd(&g_cursor[d4.w], 1);
    g_csr_src[p0] = s4.x;
    g_csr_src[p1] = s4.y;
    g_csr_src[p2] = s4.z;
    g_csr_src[p3] = s4.w;
}

// =============================================================================
// Fused layer with f32x2-packed accumulation (measured 41.0us): softmax +
// gather + bias + LN + ELU + skip (+ pooling on layer 3). Warp per node.
// =============================================================================
__device__ __forceinline__ float edge_p(float esrc, float edst) {
    float v = esrc + edst;
    v = fmaxf(v, 0.2f * v);
    return __expf(v);
}

__global__ void __launch_bounds__(256) gat_layer(
    const float* __restrict__ gat_b, const float* __restrict__ ln_g,
    const float* __restrict__ ln_b, const int* __restrict__ batch, int layer)
{
    int w = (blockIdx.x * blockDim.x + threadIdx.x) >> 5;
    int lane = threadIdx.x & 31;
    if (w >= N_NODES) return;

    float ed = __ldg(g_edst + w);

    float p = edge_p(__ldg(g_esrc + w), ed);
    float z = p;
    unsigned long long aXY = 0ull, aZW = 0ull;
    {
        ulonglong2 hs = *(const ulonglong2*)(g_hfeat + (long)w * 128 + lane * 4);
        unsigned long long pp = pk2(p, p);
        fma2(aXY, pp, hs.x);
        fma2(aZW, pp, hs.y);
    }

    int i   = __ldg(g_rowstart + w);
    int end = __ldg(g_rowstart + w + 1);

    for (; i + 4 <= end; i += 4) {
        int s0 = __ldg(g_csr_src + i);
        int s1 = __ldg(g_csr_src + i + 1);
        int s2 = __ldg(g_csr_src + i + 2);
        int s3 = __ldg(g_csr_src + i + 3);
        float p0 = edge_p(__ldg(g_esrc + s0), ed);
        float p1 = edge_p(__ldg(g_esrc + s1), ed);
        float p2 = edge_p(__ldg(g_esrc + s2), ed);
        float p3 = edge_p(__ldg(g_esrc + s3), ed);
        ulonglong2 h0 = *(const ulonglong2*)(g_hfeat + (long)s0 * 128 + lane * 4);
        ulonglong2 h1 = *(const ulonglong2*)(g_hfeat + (long)s1 * 128 + lane * 4);
        ulonglong2 h2 = *(const ulonglong2*)(g_hfeat + (long)s2 * 128 + lane * 4);
        ulonglong2 h3 = *(const ulonglong2*)(g_hfeat + (long)s3 * 128 + lane * 4);
        z += (p0 + p1) + (p2 + p3);
        unsigned long long q0 = pk2(p0, p0);
        unsigned long long q1 = pk2(p1, p1);
        unsigned long long q2 = pk2(p2, p2);
        unsigned long long q3 = pk2(p3, p3);
        fma2(aXY, q0, h0.x); fma2(aZW, q0, h0.y);
        fma2(aXY, q1, h1.x); fma2(aZW, q1, h1.y);
        fma2(aXY, q2, h2.x); fma2(aZW, q2, h2.y);
        fma2(aXY, q3, h3.x); fma2(aZW, q3, h3.y);
    }
    for (; i < end; i++) {
        int s0 = __ldg(g_csr_src + i);
        float p0 = edge_p(__ldg(g_esrc + s0), ed);
        ulonglong2 h0 = *(const ulonglong2*)(g_hfeat + (long)s0 * 128 + lane * 4);
        z += p0;
        unsigned long long q0 = pk2(p0, p0);
        fma2(aXY, q0, h0.x); fma2(aZW, q0, h0.y);
    }

    float2 axy = upk2(aXY);
    float2 azw = upk2(aZW);
    float inv = __fdividef(1.f, z);
    float4 b4 = *(const float4*)(gat_b + lane * 4);
    float4 v;
    v.x = axy.x * inv + b4.x;
    v.y = axy.y * inv + b4.y;
    v.z = azw.x * inv + b4.z;
    v.w = azw.y * inv + b4.w;

    float s  = v.x + v.y + v.z + v.w;
    float sq = v.x * v.x + v.y * v.y + v.z * v.z + v.w * v.w;
#pragma unroll
    for (int o = 16; o > 0; o >>= 1) {
        s  += __shfl_xor_sync(0xffffffff, s,  o);
        sq += __shfl_xor_sync(0xffffffff, sq, o);
    }
    float mean = s * (1.f / 128.f);
    float var  = sq * (1.f / 128.f) - mean * mean;
    float rstd = rsqrtf(var + LN_EPS);

    float4 g4 = *(const float4*)(ln_g + lane * 4);
    float4 l4 = *(const float4*)(ln_b + lane * 4);
    float y0 = (v.x - mean) * rstd * g4.x + l4.x;
    float y1 = (v.y - mean) * rstd * g4.y + l4.y;
    float y2 = (v.z - mean) * rstd * g4.z + l4.z;
    float y3 = (v.w - mean) * rstd * g4.w + l4.w;

    if (layer < 3) {
        y0 = y0 > 0.f ? y0 : expm1f(y0);
        y1 = y1 > 0.f ? y1 : expm1f(y1);
        y2 = y2 > 0.f ? y2 : expm1f(y2);
        y3 = y3 > 0.f ? y3 : expm1f(y3);
    }

    const float* skp = (layer == 0) ? g_skip : g_hcur;
    float4 sk = *(const float4*)(skp + (long)w * 128 + lane * 4);
    y0 += sk.x; y1 += sk.y; y2 += sk.z; y3 += sk.w;

    *(float4*)(g_hcur + (long)w * 128 + lane * 4) = make_float4(y0, y1, y2, y3);

    if (layer == 3) {
        int g = __ldg(batch + w);
        redAddV4(g_psum + g * 128 + lane * 4, y0, y1, y2, y3);
        float* pm = g_pmax + g * 128 + lane * 4;
        atomicMaxF(pm + 0, y0);
        atomicMaxF(pm + 1, y1);
        atomicMaxF(pm + 2, y2);
        atomicMaxF(pm + 3, y3);
        if (lane == 0) atomicAdd(&g_cnt[g], 1.f);
    }
}

// ---------------- MLP head (one block per graph) ------------------------------
__global__ void __launch_bounds__(128) mlp_head(
    const float* __restrict__ W1, const float* __restrict__ b1,
    const float* __restrict__ W2, const float* __restrict__ b2,
    const float* __restrict__ W3, const float* __restrict__ b3,
    float* __restrict__ out)
{
    __shared__ float gv[256];
    __shared__ float h1[128];
    __shared__ float h2[64];
    int g = blockIdx.x, t = threadIdx.x;

    float cnt = fmaxf(g_cnt[g], 1.f);
    gv[t]       = g_psum[g * 128 + t] / cnt;
    gv[128 + t] = g_pmax[g * 128 + t];
    __syncthreads();

    float a1 = b1[t];
#pragma unroll 8
    for (int k = 0; k < 256; k++) a1 += gv[k] * W1[k * 128 + t];
    h1[t] = fmaxf(a1, 0.f);
    __syncthreads();

    if (t < 64) {
        float a2 = b2[t];
#pragma unroll 8
        for (int k = 0; k < 128; k++) a2 += h1[k] * W2[k * 64 + t];
        h2[t] = fmaxf(a2, 0.f);
    }
    __syncthreads();

    if (t < 4) {
        float a3 = b3[t];
#pragma unroll
        for (int k = 0; k < 64; k++) a3 += h2[k] * W3[k * 4 + t];
        out[g * 4 + t] = a3;
    }
}

// ---------------- launch ------------------------------------------------------
extern "C" void kernel_launch(void* const* d_in, const int* in_sizes, int n_in,
                              void* d_out, int out_size)
{
    const float* x      = (const float*)d_in[0];
    const int*   ei     = (const int*)  d_in[1];
    const int*   batch  = (const int*)  d_in[2];
    const float* Ws     = (const float*)d_in[3];
    const float* a_src  = (const float*)d_in[4];
    const float* a_dst  = (const float*)d_in[5];
    const float* gat_b  = (const float*)d_in[6];
    const float* ln_g   = (const float*)d_in[7];
    const float* ln_b   = (const float*)d_in[8];
    const float* skip_W = (const float*)d_in[9];
    const float* skip_b = (const float*)d_in[10];
    const float* W1 = (const float*)d_in[11];
    const float* b1 = (const float*)d_in[12];
    const float* W2 = (const float*)d_in[13];
    const float* b2 = (const float*)d_in[14];
    const float* W3 = (const float*)d_in[15];
    const float* b3 = (const float*)d_in[16];

    float *hcur, *hfeat, *skip, *esrc, *edst;
    cudaGetSymbolAddress((void**)&hcur,  g_hcur);
    cudaGetSymbolAddress((void**)&hfeat, g_hfeat);
    cudaGetSymbolAddress((void**)&skip,  g_skip);
    cudaGetSymbolAddress((void**)&esrc,  g_esrc);
    cudaGetSymbolAddress((void**)&edst,  g_edst);

    const int gemm_blocks  = (N_NODES + 63) / 64;
    const int node_blocks  = (N_NODES * 32 + 255) / 256;   // warp per node
    const int nn_blocks    = (N_NODES + 255) / 256;
    const int edge4_blocks = (N_EDGES / 4 + 255) / 256;

    // lazily-created aux stream + fork/join events (host objects only)
    static cudaStream_t s_aux = nullptr;
    static cudaEvent_t  s_fork = nullptr, s_join = nullptr;
    if (!s_aux) {
        cudaStreamCreateWithFlags(&s_aux, cudaStreamNonBlocking);
        cudaEventCreateWithFlags(&s_fork, cudaEventDisableTiming);
        cudaEventCreateWithFlags(&s_join, cudaEventDisableTiming);
    }

    // fork: barrier-free CSR chain (aux) || dual GEMM (main). No data deps.
    cudaEventRecord(s_fork, 0);
    cudaStreamWaitEvent(s_aux, s_fork, 0);
    csr_zero   <<<nn_blocks, 256, 0, s_aux>>>();
    csr_hist   <<<edge4_blocks, 256, 0, s_aux>>>(ei);
    csr_scan1  <<<SCAN_BLK, 1024, 0, s_aux>>>();
    csr_scan2  <<<1, 64, 0, s_aux>>>();
    csr_scan3  <<<nn_blocks, 256, 0, s_aux>>>();
    csr_scatter<<<edge4_blocks, 256, 0, s_aux>>>(ei);
    cudaEventRecord(s_join, s_aux);

    gemm128_dual<<<gemm_blocks, 256>>>(x, Ws, skip_W, skip_b,
                                       a_src, a_dst,
                                       hfeat, skip, esrc, edst, N_NODES);

    // join: gat_layer(0) needs BOTH csr and dual results
    cudaStreamWaitEvent(0, s_join, 0);
    gat_layer<<<node_blocks, 256>>>(gat_b, ln_g, ln_b, batch, 0);

    for (int l = 1; l < 4; l++) {
        gemm128<<<gemm_blocks, 256>>>(hcur, Ws + l * 128 * 128,
                                      a_src + l * 128, a_dst + l * 128,
                                      hfeat, esrc, edst, N_NODES);
        gat_layer<<<node_blocks, 256>>>(gat_b + l * 128, ln_g + l * 128,
                                        ln_b + l * 128, batch, l);
    }

    mlp_head<<<N_GRAPHS, 128>>>(W1, b1, W2, b2, W3, b3, (float*)d_out);
}